// round 11
// baseline (speedup 1.0000x reference)
#include <cuda_runtime.h>
#include <math.h>

#define NN 1024
#define MM 16000
#define TT 50
#define NPP 50
#define TWO_N 2048
#define FOUR_N 4096

// block-range boundaries inside the mega kernel
#define B_SC0    0      // [0,50)      scores
#define B_W0     50     // [50,434)    W/Wz/Wr col-GEMV (g_cnt_pre)
#define B_VO0    434    // [434,946)   Vo @ y (g_cnt_vy)
#define B_UU0    946    // [946,962)   Ur/Uz col-GEMV (g_cnt_pre)
#define B_CTX0   962    // [962,994)   ctx (softmax + c)
#define B_C0     994    // [994,1186)  Cr/Cz/C col-GEMV + gates
#define B_U0     1186   // [1186,1314) U^T(r*s) + s_new (+ zero g_pre)
#define B_AL0    1314   // [1314,1346) alpha store (needs only c-flag)
#define B_TT0    1346   // [1346,1858) t_tilde + maxout
#define B_LG0    1858   // [1858,3858) logits (full-row prefetch)
#define B_OUT0   3858   // [3858,3874) log-softmax out
#define NBLOCKS  3874

#define N_PRE_PRODUCERS 400u   // 384 W + 16 Ur/Uz
#define N_VY_PRODUCERS  512u

// ---------------- scratch (device globals; no allocation) ----------------
__device__ float g_scores[TT];
__device__ float g_attn[TT];
__device__ float g_c[TWO_N];
__device__ float g_pre[3 * NN];     // zeroed by s_new epilogue each call
__device__ float g_z[NN];
__device__ float g_rs[NN];
__device__ float g_snew[NN];
__device__ float g_vy[FOUR_N];
__device__ unsigned g_tbits[TWO_N]; // t as float bits (atomicMax), zeroed in ctx
__device__ float g_logits[MM];
__device__ float g_sumexp;
__device__ unsigned g_cnt_sc;       // scores blocks done (50)
__device__ unsigned g_cnt_ctx;      // ctx blocks done (32)
__device__ unsigned g_cnt_pre;      // g_pre producers done (400)
__device__ unsigned g_cnt_vy;       // Vo blocks done (512)
__device__ unsigned g_cnt1;         // C-GEMV blocks (192)
__device__ unsigned g_cnt2;         // U blocks (128)
__device__ unsigned g_cnt_tt;       // ttilde blocks (512)
__device__ unsigned g_cnt_lg;       // logits blocks (2000)
__device__ unsigned g_cnt_out;      // out blocks (16)
__device__ volatile int g_flag_c;      // context ready
__device__ volatile int g_flag_gates;  // r/z/rs ready
__device__ volatile int g_flag_snew;   // s_new ready
__device__ volatile int g_flag_t;      // t ready

__device__ __forceinline__ float sigm(float x) { return 1.0f / (1.0f + expf(-x)); }
__device__ __forceinline__ float warp_sum(float v) {
#pragma unroll
    for (int o = 16; o > 0; o >>= 1) v += __shfl_down_sync(0xffffffffu, v, o);
    return v;
}
__device__ __forceinline__ float dot4(float4 a, float4 b) {
    return a.x * b.x + a.y * b.y + a.z * b.z + a.w * b.w;
}
__device__ __forceinline__ void spin_flag(volatile int* f) {
    if (threadIdx.x == 0) { while (*f == 0) { } }
    __syncthreads();
    __threadfence();
}
__device__ __forceinline__ void spin_cnt(unsigned* c, unsigned target) {
    if (threadIdx.x == 0) { while (*(volatile unsigned*)c != target) { } }
    __syncthreads();
    __threadfence();
}
// producer completion: all threads' prior global writes visible, then count
__device__ __forceinline__ void mark_done(unsigned* c) {
    __threadfence();
    __syncthreads();
    if (threadIdx.x == 0) atomicAdd(c, 1u);
}

// =====================================================================
// The whole decoder step in ONE kernel. Every cross-range dependency is
// protected by a counted flag (no dispatch-order assumptions).
// =====================================================================
__global__ void __launch_bounds__(256, 4) k_all(
    const float* __restrict__ W, const float* __restrict__ Wz,
    const float* __restrict__ Wr, const float* __restrict__ y,
    const float* __restrict__ Vo,
    const float* __restrict__ Wa, const float* __restrict__ Ua,
    const float* __restrict__ Va, const float* __restrict__ s,
    const float* __restrict__ h,
    const float* __restrict__ Ur, const float* __restrict__ Uz,
    const float* __restrict__ Cr, const float* __restrict__ Cz,
    const float* __restrict__ C,  const float* __restrict__ U,
    const float* __restrict__ Uo, const float* __restrict__ Co,
    const float* __restrict__ Wo,
    float* __restrict__ out_alpha, float* __restrict__ out)
{
    __shared__ float4 s_buf[2048];   // 32KB: logits second-half prefetch
    int b = blockIdx.x;
    int tid = threadIdx.x;
    int lane = tid & 31;
    int wib = tid >> 5;

    if (b < B_W0) {
        // ---- attention scores ----
        int i = b;
        const float4* sv = (const float4*)s;
        const float4* hv = (const float4*)(h + (size_t)i * TWO_N);
        __shared__ float wp[8];
        float part = 0.0f;
        for (int p = wib; p < NPP; p += 8) {
            const float4* wa = (const float4*)(Wa + (size_t)p * NN);
            const float4* ua = (const float4*)(Ua + (size_t)p * TWO_N);
            float d = 0.0f;
#pragma unroll 4
            for (int k = lane; k < 256; k += 32) d += dot4(__ldg(&wa[k]), __ldg(&sv[k]));
#pragma unroll 4
            for (int k = lane; k < 512; k += 32) d += dot4(__ldg(&ua[k]), __ldg(&hv[k]));
            d = warp_sum(d);
            if (lane == 0) part += __ldg(Va + p) * tanhf(d);
        }
        if (lane == 0) wp[wib] = part;
        __syncthreads();
        if (tid == 0) {
            float t = 0.0f;
#pragma unroll
            for (int k = 0; k < 8; ++k) t += wp[k];
            g_scores[i] = t;
            __threadfence();
            atomicAdd(&g_cnt_sc, 1u);
        }
    } else if (b < B_VO0) {
        // ---- pre_{r,z,w} += {Wr,Wz,W}^T y ----
        int bb = b - B_W0;
        int mat = bb >> 7;
        int chunk = bb & 127;
        const float* A = (mat == 0) ? Wr : (mat == 1) ? Wz : W;
        float* o = g_pre + mat * NN;
        const float4* A4 = (const float4*)A;
        int m0 = chunk * 125;
        float4 acc = make_float4(0.f, 0.f, 0.f, 0.f);
#pragma unroll 5
        for (int m = m0; m < m0 + 125; ++m) {
            float ym = __ldg(y + m);
            float4 a = __ldcs(&A4[(size_t)m * 256 + tid]);
            acc.x += ym * a.x; acc.y += ym * a.y; acc.z += ym * a.z; acc.w += ym * a.w;
        }
        atomicAdd(&o[4 * tid + 0], acc.x);
        atomicAdd(&o[4 * tid + 1], acc.y);
        atomicAdd(&o[4 * tid + 2], acc.z);
        atomicAdd(&o[4 * tid + 3], acc.w);
        mark_done(&g_cnt_pre);
    } else if (b < B_UU0) {
        // ---- g_vy = Vo @ y ----
        int w = ((b - B_VO0) * 256 + tid) >> 5;
        const float4* row = (const float4*)(Vo + (size_t)w * MM);
        const float4* yv = (const float4*)y;
        float d = 0.0f;
#pragma unroll 5
        for (int it = 0; it < 125; ++it) {
            int idx = lane + 32 * it;
            d += dot4(__ldcs(&row[idx]), __ldg(&yv[idx]));
        }
        d = warp_sum(d);
        if (lane == 0) g_vy[w] = d;
        mark_done(&g_cnt_vy);
    } else if (b < B_CTX0) {
        // ---- pre_r += Ur^T s ; pre_z += Uz^T s ----
        int bb = b - B_UU0;
        int mat = bb >> 3;
        int chunk = bb & 7;
        const float* A = (mat == 0) ? Ur : Uz;
        float* o = g_pre + mat * NN;
        const float4* A4 = (const float4*)A;
        int m0 = chunk * 128;
        float4 acc = make_float4(0.f, 0.f, 0.f, 0.f);
#pragma unroll 8
        for (int m = m0; m < m0 + 128; ++m) {
            float vm = __ldg(s + m);
            float4 a = __ldcs(&A4[(size_t)m * 256 + tid]);
            acc.x += vm * a.x; acc.y += vm * a.y; acc.z += vm * a.z; acc.w += vm * a.w;
        }
        atomicAdd(&o[4 * tid + 0], acc.x);
        atomicAdd(&o[4 * tid + 1], acc.y);
        atomicAdd(&o[4 * tid + 2], acc.z);
        atomicAdd(&o[4 * tid + 3], acc.w);
        mark_done(&g_cnt_pre);
    } else if (b < B_C0) {
        // ---- ctx: softmax + context c ----
        int bb = b - B_CTX0;   // 0..31
        __shared__ float sc[TT];
        __shared__ float red[256];
        spin_cnt(&g_cnt_sc, 50u);
        if (tid < 64) g_tbits[bb * 64 + tid] = 0u;   // zero t for maxout
        if (bb == 0 && tid == 0) g_sumexp = 0.0f;
        if (tid < TT) sc[tid] = g_scores[tid];
        __syncthreads();
        float mx = -1e30f;
#pragma unroll
        for (int i = 0; i < TT; ++i) mx = fmaxf(mx, sc[i]);
        float sum = 0.0f;
#pragma unroll
        for (int i = 0; i < TT; ++i) sum += expf(sc[i] - mx);
        float inv = 1.0f / sum;
        if (bb == 0 && tid < TT) g_attn[tid] = expf(sc[tid] - mx) * inv;

        int jj = tid & 63;
        int grp = tid >> 6;
        int j = bb * 64 + jj;
        float cj = 0.0f;
        for (int i = grp; i < TT; i += 4) {
            float a = expf(sc[i] - mx) * inv;
            cj += __ldg(h + (size_t)i * TWO_N + j) * a;
        }
        red[tid] = cj;
        __syncthreads();
        if (grp == 0)
            g_c[j] = red[jj] + red[64 + jj] + red[128 + jj] + red[192 + jj];
        __threadfence();
        __syncthreads();
        if (tid == 0) {
            if (atomicAdd(&g_cnt_ctx, 1u) == 31u) { __threadfence(); g_flag_c = 1; }
        }
    } else if (b < B_U0) {
        // ---- {Cr,Cz,C}^T c ; last block computes gates ----
        int bb = b - B_C0;
        int mat = bb / 64;
        int chunk = bb % 64;
        const float* A = (mat == 0) ? Cr : (mat == 1) ? Cz : C;
        const float4* A4 = (const float4*)A;
        int m0 = chunk * 32;
        spin_flag(&g_flag_c);
        float4 acc = make_float4(0.f, 0.f, 0.f, 0.f);
#pragma unroll 8
        for (int m = m0; m < m0 + 32; ++m) {
            float vm = g_c[m];
            float4 a = __ldcs(&A4[(size_t)m * 256 + tid]);
            acc.x += vm * a.x; acc.y += vm * a.y; acc.z += vm * a.z; acc.w += vm * a.w;
        }
        float* o = g_pre + mat * NN;
        atomicAdd(&o[4 * tid + 0], acc.x);
        atomicAdd(&o[4 * tid + 1], acc.y);
        atomicAdd(&o[4 * tid + 2], acc.z);
        atomicAdd(&o[4 * tid + 3], acc.w);

        __shared__ unsigned s_last;
        __threadfence();
        __syncthreads();
        if (tid == 0) s_last = (atomicAdd(&g_cnt1, 1u) == 191u) ? 1u : 0u;
        __syncthreads();
        if (s_last) {
            // all g_pre producers (W + Ur/Uz) must have landed their adds
            spin_cnt(&g_cnt_pre, N_PRE_PRODUCERS);
            for (int n = tid; n < NN; n += 256) {
                float r = sigm(g_pre[n]);
                g_z[n] = sigm(g_pre[NN + n]);
                g_rs[n] = r * __ldg(s + n);
            }
            __threadfence();
            __syncthreads();
            if (tid == 0) g_flag_gates = 1;
        }
    } else if (b < B_AL0) {
        // ---- pre_w += U^T(r*s); last block: s_new + zero g_pre ----
        int bb = b - B_U0;     // 0..127, 8 rows each
        int m0 = bb * 8;
        const float4* A4 = (const float4*)U;
        float4 a[8];
#pragma unroll
        for (int i = 0; i < 8; ++i)
            a[i] = __ldcs(&A4[(size_t)(m0 + i) * 256 + tid]);
        spin_flag(&g_flag_gates);
        float4 acc = make_float4(0.f, 0.f, 0.f, 0.f);
#pragma unroll
        for (int i = 0; i < 8; ++i) {
            float vm = g_rs[m0 + i];
            acc.x += vm * a[i].x; acc.y += vm * a[i].y;
            acc.z += vm * a[i].z; acc.w += vm * a[i].w;
        }
        float* o = g_pre + 2 * NN;
        atomicAdd(&o[4 * tid + 0], acc.x);
        atomicAdd(&o[4 * tid + 1], acc.y);
        atomicAdd(&o[4 * tid + 2], acc.z);
        atomicAdd(&o[4 * tid + 3], acc.w);

        __shared__ unsigned s_last;
        __threadfence();
        __syncthreads();
        if (tid == 0) s_last = (atomicAdd(&g_cnt2, 1u) == 127u) ? 1u : 0u;
        __syncthreads();
        if (s_last) {
            for (int n = tid; n < NN; n += 256) {
                float st = sigm(g_pre[2 * NN + n]);
                float z = g_z[n];
                float sn = (1.0f - z) * __ldg(s + n) + z * st;
                g_snew[n] = sn;
                out[MM + n] = sn;
            }
            __syncthreads();
            // zero g_pre for the next call; all producers counted-done and
            // all consumers (gates/this block) have read it.
            for (int n = tid; n < 3 * NN; n += 256) g_pre[n] = 0.0f;
            __threadfence();
            __syncthreads();
            if (tid == 0) g_flag_snew = 1;
        }
    } else if (b < B_TT0) {
        // ---- alpha store (needs only attn weights -> c-flag) ----
        int bb = b - B_AL0;    // 0..31
        spin_flag(&g_flag_c);
        int jj = tid & 63;
        int grp = tid >> 6;
        int j = bb * 64 + jj;
        for (int i = grp; i < TT; i += 4) {
            float av = __ldg(h + (size_t)i * TWO_N + j) * g_attn[i];
            out_alpha[(size_t)i * TWO_N + j] = av;
        }
    } else if (b < B_LG0) {
        // ---- t_tilde + maxout, row per warp ----
        int row = (b - B_TT0) * 8 + wib;   // 0..4095
        const float4* uo = (const float4*)(Uo + (size_t)row * NN);
        const float4* co = (const float4*)(Co + (size_t)row * TWO_N);
        // prefetch the Uo row (consumed only after snew)
        float4 a[8];
#pragma unroll
        for (int i = 0; i < 8; ++i) a[i] = __ldcs(&uo[lane + 32 * i]);
        // c is ready much earlier: stream Co·c now (overlaps phase 2)
        spin_flag(&g_flag_c);
        const float4* cv = (const float4*)g_c;
        float d = 0.0f;
#pragma unroll
        for (int it = 0; it < 16; ++it) {
            int idx = lane + 32 * it;
            d += dot4(__ldcs(&co[idx]), cv[idx]);
        }
        spin_flag(&g_flag_snew);
        spin_cnt(&g_cnt_vy, N_VY_PRODUCERS);   // g_vy fully written
        const float4* snv = (const float4*)g_snew;
#pragma unroll
        for (int i = 0; i < 8; ++i) d += dot4(a[i], snv[lane + 32 * i]);
        d = warp_sum(d);
        if (lane == 0) {
            float sig = sigm(d + g_vy[row]);
            atomicMax(&g_tbits[row >> 1], __float_as_uint(sig));
        }
        __syncthreads();
        if (tid == 0) {
            __threadfence();
            if (atomicAdd(&g_cnt_tt, 1u) == 511u) { __threadfence(); g_flag_t = 1; }
        }
    } else if (b < B_OUT0) {
        // ---- logits = Wo @ t + partial sum(exp); FULL row prefetched
        //      (first half regs, second half smem) before the t spin ----
        __shared__ float se[8];
        int w = ((b - B_LG0) * 256 + tid) >> 5;
        const float4* row4 = (const float4*)(Wo + (size_t)w * TWO_N);
        float4 pre[8];
#pragma unroll
        for (int i = 0; i < 8; ++i) pre[i] = __ldcs(&row4[lane + 32 * i]);
        float4* sb = &s_buf[wib * 256];
#pragma unroll
        for (int i = 0; i < 8; ++i) sb[lane + 32 * i] = __ldcs(&row4[256 + lane + 32 * i]);
        spin_flag(&g_flag_t);
        const float4* tv = (const float4*)g_tbits;
        float d = 0.0f;
#pragma unroll
        for (int i = 0; i < 8; ++i) d += dot4(pre[i], tv[lane + 32 * i]);
#pragma unroll
        for (int i = 0; i < 8; ++i) {
            int idx = lane + 32 * i;
            d += dot4(sb[idx], tv[256 + idx]);
        }
        d = warp_sum(d);
        if (lane == 0) { g_logits[w] = d; se[wib] = expf(d); }
        __syncthreads();
        if (tid == 0) {
            float t = se[0] + se[1] + se[2] + se[3] + se[4] + se[5] + se[6] + se[7];
            atomicAdd(&g_sumexp, t);
            __threadfence();
            atomicAdd(&g_cnt_lg, 1u);
        }
    } else {
        // ---- out = logits - log(sumexp); last block resets state ----
        int bb = b - B_OUT0;   // 0..15
        spin_cnt(&g_cnt_lg, 2000u);
        float lse = logf(g_sumexp);
        for (int m = bb * 256 + tid; m < MM; m += 4096)
            out[m] = g_logits[m] - lse;
        __syncthreads();
        if (tid == 0) {
            if (atomicAdd(&g_cnt_out, 1u) == 15u) {
                g_cnt_sc = 0u; g_cnt_ctx = 0u; g_cnt_pre = 0u; g_cnt_vy = 0u;
                g_cnt1 = 0u; g_cnt2 = 0u;
                g_cnt_tt = 0u; g_cnt_lg = 0u; g_cnt_out = 0u;
                g_flag_c = 0; g_flag_gates = 0; g_flag_snew = 0; g_flag_t = 0;
            }
        }
    }
}

// ---------------- launch ----------------
extern "C" void kernel_launch(void* const* d_in, const int* in_sizes, int n_in,
                              void* d_out, int out_size) {
    const float* y  = (const float*)d_in[0];
    const float* s  = (const float*)d_in[1];
    const float* h  = (const float*)d_in[2];
    const float* W  = (const float*)d_in[3];
    const float* Wz = (const float*)d_in[4];
    const float* Wr = (const float*)d_in[5];
    const float* Wo = (const float*)d_in[6];
    const float* U  = (const float*)d_in[7];
    const float* Uz = (const float*)d_in[8];
    const float* Ur = (const float*)d_in[9];
    const float* Uo = (const float*)d_in[10];
    const float* C  = (const float*)d_in[11];
    const float* Cz = (const float*)d_in[12];
    const float* Cr = (const float*)d_in[13];
    const float* Co = (const float*)d_in[14];
    const float* Vo = (const float*)d_in[15];
    const float* Va = (const float*)d_in[16];
    const float* Wa = (const float*)d_in[17];
    const float* Ua = (const float*)d_in[18];
    float* out = (float*)d_out;

    k_all<<<NBLOCKS, 256>>>(W, Wz, Wr, y, Vo, Wa, Ua, Va, s, h, Ur, Uz,
                            Cr, Cz, C, U, Uo, Co, Wo,
                            out + MM + NN, out);
}

// round 12
// speedup vs baseline: 1.0667x; 1.0667x over previous
#include <cuda_runtime.h>
#include <math.h>

#define NN 1024
#define MM 16000
#define TT 50
#define NPP 50
#define TWO_N 2048
#define FOUR_N 4096

// block-range boundaries inside the mega kernel
#define B_SC0    0      // [0,50)      scores
#define B_W0     50     // [50,434)    W/Wz/Wr col-GEMV (g_cnt_pre)
#define B_VO0    434    // [434,946)   Vo @ y (per-block g_vy_done)
#define B_UU0    946    // [946,962)   Ur/Uz col-GEMV (g_cnt_pre)
#define B_CTX0   962    // [962,994)   ctx (softmax + c)
#define B_C0     994    // [994,1186)  Cr/Cz/C col-GEMV + gates
#define B_U0     1186   // [1186,1314) U^T(r*s) + s_new (+ zero g_pre)
#define B_AL0    1314   // [1314,1346) alpha store (needs only c-flag)
#define B_TT0    1346   // [1346,1858) t_tilde + maxout
#define B_LG0    1858   // [1858,3858) logits (regs half-row prefetch)
#define B_OUT0   3858   // [3858,3874) log-softmax out
#define NBLOCKS  3874

#define N_PRE_PRODUCERS 400u   // 384 W + 16 Ur/Uz

// ---------------- scratch (device globals; no allocation) ----------------
__device__ float g_scores[TT];
__device__ float g_attn[TT];
__device__ float g_c[TWO_N];
__device__ float g_pre[3 * NN];     // zeroed by s_new epilogue each call
__device__ float g_z[NN];
__device__ float g_rs[NN];
__device__ float g_snew[NN];
__device__ float g_vy[FOUR_N];
__device__ unsigned g_vy_done[512]; // per-Vo-block completion (reset by out blocks)
__device__ unsigned g_tbits[TWO_N]; // t as float bits (atomicMax), zeroed in ctx
__device__ float g_logits[MM];
__device__ float g_sumexp;
__device__ unsigned g_cnt_sc;       // scores blocks done (50)
__device__ unsigned g_cnt_ctx;      // ctx blocks done (32)
__device__ unsigned g_cnt_pre;      // g_pre producers done (400)
__device__ unsigned g_cnt1;         // C-GEMV blocks (192)
__device__ unsigned g_cnt2;         // U blocks (128)
__device__ unsigned g_cnt_tt;       // ttilde blocks (512)
__device__ unsigned g_cnt_lg;       // logits blocks (2000)
__device__ unsigned g_cnt_out;      // out blocks (16)
__device__ volatile int g_flag_c;      // context ready
__device__ volatile int g_flag_gates;  // r/z/rs ready
__device__ volatile int g_flag_snew;   // s_new ready
__device__ volatile int g_flag_t;      // t ready

__device__ __forceinline__ float sigm(float x) { return 1.0f / (1.0f + expf(-x)); }
__device__ __forceinline__ float warp_sum(float v) {
#pragma unroll
    for (int o = 16; o > 0; o >>= 1) v += __shfl_down_sync(0xffffffffu, v, o);
    return v;
}
__device__ __forceinline__ float dot4(float4 a, float4 b) {
    return a.x * b.x + a.y * b.y + a.z * b.z + a.w * b.w;
}
__device__ __forceinline__ void spin_flag(volatile int* f) {
    if (threadIdx.x == 0) { while (*f == 0) { } }
    __syncthreads();
    __threadfence();
}
__device__ __forceinline__ void spin_cnt(unsigned* c, unsigned target) {
    if (threadIdx.x == 0) { while (*(volatile unsigned*)c != target) { } }
    __syncthreads();
    __threadfence();
}
// producer completion: all threads' prior global writes visible, then count
__device__ __forceinline__ void mark_done(unsigned* c) {
    __threadfence();
    __syncthreads();
    if (threadIdx.x == 0) atomicAdd(c, 1u);
}

// =====================================================================
// The whole decoder step in ONE kernel. Every cross-range dependency is
// protected by a counted flag (no dispatch-order assumptions).
// =====================================================================
__global__ void __launch_bounds__(256, 4) k_all(
    const float* __restrict__ W, const float* __restrict__ Wz,
    const float* __restrict__ Wr, const float* __restrict__ y,
    const float* __restrict__ Vo,
    const float* __restrict__ Wa, const float* __restrict__ Ua,
    const float* __restrict__ Va, const float* __restrict__ s,
    const float* __restrict__ h,
    const float* __restrict__ Ur, const float* __restrict__ Uz,
    const float* __restrict__ Cr, const float* __restrict__ Cz,
    const float* __restrict__ C,  const float* __restrict__ U,
    const float* __restrict__ Uo, const float* __restrict__ Co,
    const float* __restrict__ Wo,
    float* __restrict__ out_alpha, float* __restrict__ out)
{
    int b = blockIdx.x;
    int tid = threadIdx.x;
    int lane = tid & 31;
    int wib = tid >> 5;

    if (b < B_W0) {
        // ---- attention scores ----
        int i = b;
        const float4* sv = (const float4*)s;
        const float4* hv = (const float4*)(h + (size_t)i * TWO_N);
        __shared__ float wp[8];
        float part = 0.0f;
        for (int p = wib; p < NPP; p += 8) {
            const float4* wa = (const float4*)(Wa + (size_t)p * NN);
            const float4* ua = (const float4*)(Ua + (size_t)p * TWO_N);
            float d = 0.0f;
#pragma unroll 4
            for (int k = lane; k < 256; k += 32) d += dot4(__ldg(&wa[k]), __ldg(&sv[k]));
#pragma unroll 4
            for (int k = lane; k < 512; k += 32) d += dot4(__ldg(&ua[k]), __ldg(&hv[k]));
            d = warp_sum(d);
            if (lane == 0) part += __ldg(Va + p) * tanhf(d);
        }
        if (lane == 0) wp[wib] = part;
        __syncthreads();
        if (tid == 0) {
            float t = 0.0f;
#pragma unroll
            for (int k = 0; k < 8; ++k) t += wp[k];
            g_scores[i] = t;
            __threadfence();
            atomicAdd(&g_cnt_sc, 1u);
        }
    } else if (b < B_VO0) {
        // ---- pre_{r,z,w} += {Wr,Wz,W}^T y ----
        int bb = b - B_W0;
        int mat = bb >> 7;
        int chunk = bb & 127;
        const float* A = (mat == 0) ? Wr : (mat == 1) ? Wz : W;
        float* o = g_pre + mat * NN;
        const float4* A4 = (const float4*)A;
        int m0 = chunk * 125;
        float4 acc = make_float4(0.f, 0.f, 0.f, 0.f);
#pragma unroll 5
        for (int m = m0; m < m0 + 125; ++m) {
            float ym = __ldg(y + m);
            float4 a = __ldcs(&A4[(size_t)m * 256 + tid]);
            acc.x += ym * a.x; acc.y += ym * a.y; acc.z += ym * a.z; acc.w += ym * a.w;
        }
        atomicAdd(&o[4 * tid + 0], acc.x);
        atomicAdd(&o[4 * tid + 1], acc.y);
        atomicAdd(&o[4 * tid + 2], acc.z);
        atomicAdd(&o[4 * tid + 3], acc.w);
        mark_done(&g_cnt_pre);
    } else if (b < B_UU0) {
        // ---- g_vy = Vo @ y (per-block done flag) ----
        int bb = b - B_VO0;   // 0..511
        int w = (bb * 256 + tid) >> 5;
        const float4* row = (const float4*)(Vo + (size_t)w * MM);
        const float4* yv = (const float4*)y;
        float d = 0.0f;
#pragma unroll 5
        for (int it = 0; it < 125; ++it) {
            int idx = lane + 32 * it;
            d += dot4(__ldcs(&row[idx]), __ldg(&yv[idx]));
        }
        d = warp_sum(d);
        if (lane == 0) g_vy[w] = d;
        __threadfence();
        __syncthreads();
        if (tid == 0) g_vy_done[bb] = 1u;
    } else if (b < B_CTX0) {
        // ---- pre_r += Ur^T s ; pre_z += Uz^T s ----
        int bb = b - B_UU0;
        int mat = bb >> 3;
        int chunk = bb & 7;
        const float* A = (mat == 0) ? Ur : Uz;
        float* o = g_pre + mat * NN;
        const float4* A4 = (const float4*)A;
        int m0 = chunk * 128;
        float4 acc = make_float4(0.f, 0.f, 0.f, 0.f);
#pragma unroll 8
        for (int m = m0; m < m0 + 128; ++m) {
            float vm = __ldg(s + m);
            float4 a = __ldcs(&A4[(size_t)m * 256 + tid]);
            acc.x += vm * a.x; acc.y += vm * a.y; acc.z += vm * a.z; acc.w += vm * a.w;
        }
        atomicAdd(&o[4 * tid + 0], acc.x);
        atomicAdd(&o[4 * tid + 1], acc.y);
        atomicAdd(&o[4 * tid + 2], acc.z);
        atomicAdd(&o[4 * tid + 3], acc.w);
        mark_done(&g_cnt_pre);
    } else if (b < B_C0) {
        // ---- ctx: softmax + context c ----
        int bb = b - B_CTX0;   // 0..31
        __shared__ float sc[TT];
        __shared__ float red[256];
        spin_cnt(&g_cnt_sc, 50u);
        if (tid < 64) g_tbits[bb * 64 + tid] = 0u;   // zero t for maxout
        if (bb == 0 && tid == 0) g_sumexp = 0.0f;
        if (tid < TT) sc[tid] = g_scores[tid];
        __syncthreads();
        float mx = -1e30f;
#pragma unroll
        for (int i = 0; i < TT; ++i) mx = fmaxf(mx, sc[i]);
        float sum = 0.0f;
#pragma unroll
        for (int i = 0; i < TT; ++i) sum += expf(sc[i] - mx);
        float inv = 1.0f / sum;
        if (bb == 0 && tid < TT) g_attn[tid] = expf(sc[tid] - mx) * inv;

        int jj = tid & 63;
        int grp = tid >> 6;
        int j = bb * 64 + jj;
        float cj = 0.0f;
        for (int i = grp; i < TT; i += 4) {
            float a = expf(sc[i] - mx) * inv;
            cj += __ldg(h + (size_t)i * TWO_N + j) * a;
        }
        red[tid] = cj;
        __syncthreads();
        if (grp == 0)
            g_c[j] = red[jj] + red[64 + jj] + red[128 + jj] + red[192 + jj];
        __threadfence();
        __syncthreads();
        if (tid == 0) {
            if (atomicAdd(&g_cnt_ctx, 1u) == 31u) { __threadfence(); g_flag_c = 1; }
        }
    } else if (b < B_U0) {
        // ---- {Cr,Cz,C}^T c ; last block computes gates ----
        int bb = b - B_C0;
        int mat = bb / 64;
        int chunk = bb % 64;
        const float* A = (mat == 0) ? Cr : (mat == 1) ? Cz : C;
        const float4* A4 = (const float4*)A;
        int m0 = chunk * 32;
        spin_flag(&g_flag_c);
        float4 acc = make_float4(0.f, 0.f, 0.f, 0.f);
#pragma unroll 8
        for (int m = m0; m < m0 + 32; ++m) {
            float vm = g_c[m];
            float4 a = __ldcs(&A4[(size_t)m * 256 + tid]);
            acc.x += vm * a.x; acc.y += vm * a.y; acc.z += vm * a.z; acc.w += vm * a.w;
        }
        float* o = g_pre + mat * NN;
        atomicAdd(&o[4 * tid + 0], acc.x);
        atomicAdd(&o[4 * tid + 1], acc.y);
        atomicAdd(&o[4 * tid + 2], acc.z);
        atomicAdd(&o[4 * tid + 3], acc.w);

        __shared__ unsigned s_last;
        __threadfence();
        __syncthreads();
        if (tid == 0) s_last = (atomicAdd(&g_cnt1, 1u) == 191u) ? 1u : 0u;
        __syncthreads();
        if (s_last) {
            // all g_pre producers (W + Ur/Uz) must have landed their adds
            spin_cnt(&g_cnt_pre, N_PRE_PRODUCERS);
            for (int n = tid; n < NN; n += 256) {
                float r = sigm(g_pre[n]);
                g_z[n] = sigm(g_pre[NN + n]);
                g_rs[n] = r * __ldg(s + n);
            }
            __threadfence();
            __syncthreads();
            if (tid == 0) g_flag_gates = 1;
        }
    } else if (b < B_AL0) {
        // ---- pre_w += U^T(r*s); last block: s_new + zero g_pre ----
        int bb = b - B_U0;     // 0..127, 8 rows each
        int m0 = bb * 8;
        const float4* A4 = (const float4*)U;
        float4 a[8];
#pragma unroll
        for (int i = 0; i < 8; ++i)
            a[i] = __ldcs(&A4[(size_t)(m0 + i) * 256 + tid]);
        spin_flag(&g_flag_gates);
        float4 acc = make_float4(0.f, 0.f, 0.f, 0.f);
#pragma unroll
        for (int i = 0; i < 8; ++i) {
            float vm = g_rs[m0 + i];
            acc.x += vm * a[i].x; acc.y += vm * a[i].y;
            acc.z += vm * a[i].z; acc.w += vm * a[i].w;
        }
        float* o = g_pre + 2 * NN;
        atomicAdd(&o[4 * tid + 0], acc.x);
        atomicAdd(&o[4 * tid + 1], acc.y);
        atomicAdd(&o[4 * tid + 2], acc.z);
        atomicAdd(&o[4 * tid + 3], acc.w);

        __shared__ unsigned s_last;
        __threadfence();
        __syncthreads();
        if (tid == 0) s_last = (atomicAdd(&g_cnt2, 1u) == 127u) ? 1u : 0u;
        __syncthreads();
        if (s_last) {
            for (int n = tid; n < NN; n += 256) {
                float st = sigm(g_pre[2 * NN + n]);
                float z = g_z[n];
                float sn = (1.0f - z) * __ldg(s + n) + z * st;
                g_snew[n] = sn;
                out[MM + n] = sn;
            }
            __syncthreads();
            // zero g_pre for the next call; all producers counted-done and
            // all consumers (gates/this block) have read it.
            for (int n = tid; n < 3 * NN; n += 256) g_pre[n] = 0.0f;
            __threadfence();
            __syncthreads();
            if (tid == 0) g_flag_snew = 1;
        }
    } else if (b < B_TT0) {
        // ---- alpha store (needs only attn weights -> c-flag) ----
        int bb = b - B_AL0;    // 0..31
        spin_flag(&g_flag_c);
        int jj = tid & 63;
        int grp = tid >> 6;
        int j = bb * 64 + jj;
        for (int i = grp; i < TT; i += 4) {
            float av = __ldg(h + (size_t)i * TWO_N + j) * g_attn[i];
            out_alpha[(size_t)i * TWO_N + j] = av;
        }
    } else if (b < B_LG0) {
        // ---- t_tilde + maxout, row per warp ----
        int bb = b - B_TT0;    // 0..511  (same partition as Vo block bb)
        int row = bb * 8 + wib;
        const float4* uo = (const float4*)(Uo + (size_t)row * NN);
        const float4* co = (const float4*)(Co + (size_t)row * TWO_N);
        // prefetch the Uo row (consumed only after snew)
        float4 a[8];
#pragma unroll
        for (int i = 0; i < 8; ++i) a[i] = __ldcs(&uo[lane + 32 * i]);
        // c is ready much earlier: stream Co·c now (overlaps phase 2)
        spin_flag(&g_flag_c);
        const float4* cv = (const float4*)g_c;
        float d = 0.0f;
#pragma unroll
        for (int it = 0; it < 16; ++it) {
            int idx = lane + 32 * it;
            d += dot4(__ldcs(&co[idx]), cv[idx]);
        }
        spin_flag(&g_flag_snew);
        // wait only for OUR g_vy producer (Vo block bb), not all 512
        if (tid == 0) { while (((volatile unsigned*)g_vy_done)[bb] == 0u) { } }
        __syncthreads();
        __threadfence();
        const float4* snv = (const float4*)g_snew;
#pragma unroll
        for (int i = 0; i < 8; ++i) d += dot4(a[i], snv[lane + 32 * i]);
        d = warp_sum(d);
        if (lane == 0) {
            float sig = sigm(d + g_vy[row]);
            atomicMax(&g_tbits[row >> 1], __float_as_uint(sig));
        }
        __syncthreads();
        if (tid == 0) {
            __threadfence();
            if (atomicAdd(&g_cnt_tt, 1u) == 511u) { __threadfence(); g_flag_t = 1; }
        }
    } else if (b < B_OUT0) {
        // ---- logits = Wo @ t + partial sum(exp); first half-row
        //      prefetched into regs before the t spin ----
        __shared__ float se[8];
        int w = ((b - B_LG0) * 256 + tid) >> 5;
        const float4* row4 = (const float4*)(Wo + (size_t)w * TWO_N);
        float4 pre[8];
#pragma unroll
        for (int i = 0; i < 8; ++i) pre[i] = __ldcs(&row4[lane + 32 * i]);
        spin_flag(&g_flag_t);
        const float4* tv = (const float4*)g_tbits;
        float d = 0.0f;
#pragma unroll
        for (int i = 0; i < 8; ++i) d += dot4(pre[i], tv[lane + 32 * i]);
#pragma unroll
        for (int i = 8; i < 16; ++i) {
            int idx = lane + 32 * i;
            d += dot4(__ldcs(&row4[idx]), tv[idx]);
        }
        d = warp_sum(d);
        if (lane == 0) { g_logits[w] = d; se[wib] = expf(d); }
        __syncthreads();
        if (tid == 0) {
            float t = se[0] + se[1] + se[2] + se[3] + se[4] + se[5] + se[6] + se[7];
            atomicAdd(&g_sumexp, t);
            __threadfence();
            atomicAdd(&g_cnt_lg, 1u);
        }
    } else {
        // ---- out = logits - log(sumexp); resets state ----
        int bb = b - B_OUT0;   // 0..15
        spin_cnt(&g_cnt_lg, 2000u);
        // everything is done now: reset per-block vy flags (32 each)
        if (tid < 32) g_vy_done[bb * 32 + tid] = 0u;
        float lse = logf(g_sumexp);
        for (int m = bb * 256 + tid; m < MM; m += 4096)
            out[m] = g_logits[m] - lse;
        __syncthreads();
        if (tid == 0) {
            if (atomicAdd(&g_cnt_out, 1u) == 15u) {
                g_cnt_sc = 0u; g_cnt_ctx = 0u; g_cnt_pre = 0u;
                g_cnt1 = 0u; g_cnt2 = 0u;
                g_cnt_tt = 0u; g_cnt_lg = 0u; g_cnt_out = 0u;
                g_flag_c = 0; g_flag_gates = 0; g_flag_snew = 0; g_flag_t = 0;
            }
        }
    }
}

// ---------------- launch ----------------
extern "C" void kernel_launch(void* const* d_in, const int* in_sizes, int n_in,
                              void* d_out, int out_size) {
    const float* y  = (const float*)d_in[0];
    const float* s  = (const float*)d_in[1];
    const float* h  = (const float*)d_in[2];
    const float* W  = (const float*)d_in[3];
    const float* Wz = (const float*)d_in[4];
    const float* Wr = (const float*)d_in[5];
    const float* Wo = (const float*)d_in[6];
    const float* U  = (const float*)d_in[7];
    const float* Uz = (const float*)d_in[8];
    const float* Ur = (const float*)d_in[9];
    const float* Uo = (const float*)d_in[10];
    const float* C  = (const float*)d_in[11];
    const float* Cz = (const float*)d_in[12];
    const float* Cr = (const float*)d_in[13];
    const float* Co = (const float*)d_in[14];
    const float* Vo = (const float*)d_in[15];
    const float* Va = (const float*)d_in[16];
    const float* Wa = (const float*)d_in[17];
    const float* Ua = (const float*)d_in[18];
    float* out = (float*)d_out;

    k_all<<<NBLOCKS, 256>>>(W, Wz, Wr, y, Vo, Wa, Ua, Va, s, h, Ur, Uz,
                            Cr, Cz, C, U, Uo, Co, Wo,
                            out + MM + NN, out);
}